// round 2
// baseline (speedup 1.0000x reference)
#include <cuda_runtime.h>
#include <cuda_bf16.h>

// ---------------- problem constants ----------------
#define NB   128          // batch (graphs)
#define NPV  20           // v nodes per graph
#define NPP  500          // p nodes per graph
#define NVG  (NB*NPV)     // 2560 total v nodes
#define NPG  (NB*NPP)     // 64000 total p nodes
#define DD   256          // embedding dim
#define FV   6
#define FP   8
#define DEG  8
#define EV   (NVG*DEG)    // 20480
#define EP   (NPG*DEG)    // 512000
#define CAP  64           // CSR slots per node (in-degree ~ Binomial(4000,1/500), mean 8)
#define PPOOL 10          // p-net pooling partials per graph (500/10 = 50 nodes each)

// ---------------- static device scratch (no allocations allowed) -------------
__device__ float g_p_init[NPG*DD];
__device__ float g_p_tmp [NPG*DD];
__device__ float g_p_h   [NPG*DD];
__device__ float g_p_node[NPG*DD];

__device__ float g_v_init[NVG*DD];
__device__ float g_v_tmp [NVG*DD];
__device__ float g_v_h   [NVG*DD];
__device__ float g_v_node[NVG*DD];

__device__ int   g_p_indeg[NPG];
__device__ int   g_v_indeg[NVG];
__device__ float g_p_dinv[NPG];
__device__ float g_v_dinv[NVG];
__device__ int   g_p_csr[NPG*CAP];
__device__ int   g_v_csr[NVG*CAP];

__device__ float g_pg_part[NB*PPOOL*DD]; // p pooling partials
__device__ float g_vg[NB*DD];            // v graph emb
__device__ float g_addvec[NB*DD];        // per-batch additive vector for final fuse

// ---------------- kernels ----------------

__global__ void zero_int(int* p, int n) {
    int i = blockIdx.x * blockDim.x + threadIdx.x;
    if (i < n) p[i] = 0;
}

__global__ void build_csr(const int* __restrict__ src, const int* __restrict__ dst,
                          int E, int* __restrict__ indeg, int* __restrict__ csr) {
    int e = blockIdx.x * blockDim.x + threadIdx.x;
    if (e >= E) return;
    int d = dst[e];
    int slot = atomicAdd(&indeg[d], 1);
    if (slot < CAP) csr[d * CAP + slot] = src[e];
}

__global__ void compute_dinv(const int* __restrict__ indeg, float* __restrict__ dinv, int n) {
    int i = blockIdx.x * blockDim.x + threadIdx.x;
    if (i < n) dinv[i] = rsqrtf((float)indeg[i] + 1.0f);
}

// init_emb = x @ W + b  (K = F tiny: 6 or 8). One block per node, thread = channel.
// W reads coalesced & cache-resident (W is <= 8KB), x reads broadcast within block.
__global__ __launch_bounds__(256) void init_emb_kernel(
    const float* __restrict__ x, const float* __restrict__ W, const float* __restrict__ b,
    float* __restrict__ out, int F) {
    int node = blockIdx.x;
    int d = threadIdx.x;
    const float* xr = x + node * F;
    float acc = __ldg(&b[d]);
    #pragma unroll 8
    for (int k = 0; k < 8; k++) {
        if (k < F) acc = fmaf(__ldg(&xr[k]), __ldg(&W[k * DD + d]), acc);
    }
    out[node * DD + d] = acc;
}

// C[M,256] = A[M,256] @ B[256,256]   (row-major), 128x128x8 tile, 8x8 microtile
__global__ __launch_bounds__(256) void sgemm256(
    const float* __restrict__ A, const float* __restrict__ Bm, float* __restrict__ C, int M) {
    __shared__ float As[8][132];  // padded
    __shared__ float Bs[8][128];
    int tid = threadIdx.x;
    int row0 = blockIdx.y * 128;
    int col0 = blockIdx.x * 128;
    int tx = tid & 15, ty = tid >> 4;

    float acc[8][8];
    #pragma unroll
    for (int i = 0; i < 8; i++)
        #pragma unroll
        for (int j = 0; j < 8; j++) acc[i][j] = 0.0f;

    int arow = tid >> 1;           // 0..127
    int ahalf = (tid & 1) * 4;     // 0 or 4
    int bk = tid >> 5;             // 0..7
    int bn = (tid & 31) * 4;
    const float* Aptr = A + (row0 + arow) * DD + ahalf;
    const float* Bptr = Bm + bk * DD + col0 + bn;

    for (int kt = 0; kt < DD; kt += 8) {
        float4 a4 = *(const float4*)(Aptr + kt);
        As[ahalf + 0][arow] = a4.x;
        As[ahalf + 1][arow] = a4.y;
        As[ahalf + 2][arow] = a4.z;
        As[ahalf + 3][arow] = a4.w;
        *(float4*)&Bs[bk][bn] = *(const float4*)(Bptr + kt * DD);
        __syncthreads();
        #pragma unroll
        for (int k = 0; k < 8; k++) {
            float4 a0 = *(const float4*)&As[k][ty * 8];
            float4 a1 = *(const float4*)&As[k][ty * 8 + 4];
            float4 b0 = *(const float4*)&Bs[k][tx * 8];
            float4 b1 = *(const float4*)&Bs[k][tx * 8 + 4];
            float av[8] = {a0.x, a0.y, a0.z, a0.w, a1.x, a1.y, a1.z, a1.w};
            float bv[8] = {b0.x, b0.y, b0.z, b0.w, b1.x, b1.y, b1.z, b1.w};
            #pragma unroll
            for (int i = 0; i < 8; i++)
                #pragma unroll
                for (int j = 0; j < 8; j++)
                    acc[i][j] = fmaf(av[i], bv[j], acc[i][j]);
        }
        __syncthreads();
    }
    #pragma unroll
    for (int i = 0; i < 8; i++) {
        float4 c0 = make_float4(acc[i][0], acc[i][1], acc[i][2], acc[i][3]);
        float4 c1 = make_float4(acc[i][4], acc[i][5], acc[i][6], acc[i][7]);
        float* Cp = C + (row0 + ty * 8 + i) * DD + col0 + tx * 8;
        *(float4*)Cp = c0;
        *(float4*)(Cp + 4) = c1;
    }
}

// out[node] = bias + h[node]/deg + sum_{in-edges} h[src]*dinv[src]*dinv[dst]  (+relu)
// one warp per node, lane handles 8 contiguous channels
__global__ __launch_bounds__(256) void gcn_agg(
    const float* __restrict__ h, const int* __restrict__ csr, const int* __restrict__ indeg,
    const float* __restrict__ dinv, const float* __restrict__ bias,
    float* __restrict__ out, int n_nodes, int do_relu) {
    int warp = threadIdx.x >> 5;
    int lane = threadIdx.x & 31;
    int node = blockIdx.x * 8 + warp;
    if (node >= n_nodes) return;

    int deg = indeg[node];
    int cnt = deg < CAP ? deg : CAP;
    float degf = (float)deg + 1.0f;
    float self = 1.0f / degf;
    float ddst = dinv[node];
    int d0 = lane * 8;

    const float* hn = h + node * DD + d0;
    float4 s0 = *(const float4*)hn;
    float4 s1 = *(const float4*)(hn + 4);
    float4 acc0 = make_float4(s0.x * self, s0.y * self, s0.z * self, s0.w * self);
    float4 acc1 = make_float4(s1.x * self, s1.y * self, s1.z * self, s1.w * self);

    const int* cp = csr + node * CAP;
    for (int e = 0; e < cnt; e++) {
        int src = cp[e];
        float c = ddst * dinv[src];
        const float* hs = h + src * DD + d0;
        float4 m0 = *(const float4*)hs;
        float4 m1 = *(const float4*)(hs + 4);
        acc0.x = fmaf(c, m0.x, acc0.x);
        acc0.y = fmaf(c, m0.y, acc0.y);
        acc0.z = fmaf(c, m0.z, acc0.z);
        acc0.w = fmaf(c, m0.w, acc0.w);
        acc1.x = fmaf(c, m1.x, acc1.x);
        acc1.y = fmaf(c, m1.y, acc1.y);
        acc1.z = fmaf(c, m1.z, acc1.z);
        acc1.w = fmaf(c, m1.w, acc1.w);
    }
    float4 b0 = *(const float4*)(bias + d0);
    float4 b1 = *(const float4*)(bias + d0 + 4);
    acc0.x += b0.x; acc0.y += b0.y; acc0.z += b0.z; acc0.w += b0.w;
    acc1.x += b1.x; acc1.y += b1.y; acc1.z += b1.z; acc1.w += b1.w;
    if (do_relu) {
        acc0.x = fmaxf(acc0.x, 0.f); acc0.y = fmaxf(acc0.y, 0.f);
        acc0.z = fmaxf(acc0.z, 0.f); acc0.w = fmaxf(acc0.w, 0.f);
        acc1.x = fmaxf(acc1.x, 0.f); acc1.y = fmaxf(acc1.y, 0.f);
        acc1.z = fmaxf(acc1.z, 0.f); acc1.w = fmaxf(acc1.w, 0.f);
    }
    float* op = out + node * DD + d0;
    *(float4*)op = acc0;
    *(float4*)(op + 4) = acc1;
}

// v pooling: one block per graph (only 20 nodes), thread = channel
__global__ __launch_bounds__(256) void pool_v_kernel(
    const float* __restrict__ node_emb, float* __restrict__ g) {
    int b = blockIdx.x, d = threadIdx.x;
    const float* p = node_emb + (size_t)b * NPV * DD + d;
    float s = 0.f;
    #pragma unroll
    for (int i = 0; i < NPV; i++) s += p[i * DD];
    g[b * DD + d] = s * (1.0f / NPV);
}

// p pooling partials: grid (NB, PPOOL); each block sums 50 nodes
__global__ __launch_bounds__(256) void pool_p_partial(
    const float* __restrict__ node_emb, float* __restrict__ part) {
    int b = blockIdx.x, ppart = blockIdx.y, d = threadIdx.x;
    const int chunk = NPP / PPOOL;  // 50
    const float* p = node_emb + ((size_t)b * NPP + ppart * chunk) * DD + d;
    float s0 = 0.f, s1 = 0.f;
    #pragma unroll
    for (int i = 0; i < chunk; i += 2) {
        s0 += p[i * DD];
        s1 += p[(i + 1) * DD];
    }
    part[(b * PPOOL + ppart) * DD + d] = s0 + s1;
}

// addvec[b,d] = p_graph + 2*v_graph + v_node[b,cid] + v_init[b,cid]
// p_graph computed from the PPOOL partials here.
__global__ void addvec_kernel(const float* __restrict__ pg_part, const float* __restrict__ vg,
                              const float* __restrict__ v_node, const float* __restrict__ v_init,
                              const int* __restrict__ curr, float* __restrict__ av) {
    int b = blockIdx.x, d = threadIdx.x;
    float pgs = 0.f;
    #pragma unroll
    for (int j = 0; j < PPOOL; j++) pgs += pg_part[(b * PPOOL + j) * DD + d];
    float pgd = pgs * (1.0f / NPP);
    int cid = curr[b];
    int vi = (b * NPV + cid) * DD + d;
    av[b * DD + d] = pgd + 2.0f * vg[b * DD + d] + v_node[vi] + v_init[vi];
}

// out = p_node + p_init + addvec[b]   (float4 granularity)
__global__ void final_kernel(const float* __restrict__ pn, const float* __restrict__ pi,
                             const float* __restrict__ av, float* __restrict__ out) {
    int idx = blockIdx.x * blockDim.x + threadIdx.x;   // float4 index
    const int total4 = NPG * (DD / 4);                 // 4,096,000
    if (idx >= total4) return;
    int node = idx >> 6;          // /64
    int d4 = idx & 63;
    int b = node / NPP;
    float4 a = ((const float4*)pn)[idx];
    float4 c = ((const float4*)pi)[idx];
    float4 v = ((const float4*)av)[b * (DD / 4) + d4];
    float4 r = make_float4(a.x + c.x + v.x, a.y + c.y + v.y,
                           a.z + c.z + v.z, a.w + c.w + v.w);
    ((float4*)out)[idx] = r;
}

// ---------------- host launch ----------------
static inline void* sym(const void* s) {
    void* p = nullptr;
    cudaGetSymbolAddress(&p, s);
    return p;
}

extern "C" void kernel_launch(void* const* d_in, const int* in_sizes, int n_in,
                              void* d_out, int out_size) {
    const float* v_x     = (const float*)d_in[0];
    const float* p_x     = (const float*)d_in[1];
    const int*   v_src   = (const int*)d_in[2];
    const int*   v_dst   = (const int*)d_in[3];
    const int*   p_src   = (const int*)d_in[4];
    const int*   p_dst   = (const int*)d_in[5];
    // d_in[6]=v_batch, d_in[7]=p_batch unused (equal-size contiguous graphs)
    const int*   curr    = (const int*)d_in[8];
    const float* v_initW = (const float*)d_in[9];
    const float* v_initb = (const float*)d_in[10];
    const float* v_W1    = (const float*)d_in[11];
    const float* v_b1    = (const float*)d_in[12];
    const float* v_W2    = (const float*)d_in[13];
    const float* v_b2    = (const float*)d_in[14];
    const float* p_initW = (const float*)d_in[15];
    const float* p_initb = (const float*)d_in[16];
    const float* p_W1    = (const float*)d_in[17];
    const float* p_b1    = (const float*)d_in[18];
    const float* p_W2    = (const float*)d_in[19];
    const float* p_b2    = (const float*)d_in[20];
    float* out = (float*)d_out;

    float* p_init = (float*)sym(g_p_init);
    float* p_tmp  = (float*)sym(g_p_tmp);
    float* p_h    = (float*)sym(g_p_h);
    float* p_node = (float*)sym(g_p_node);
    float* v_init = (float*)sym(g_v_init);
    float* v_tmp  = (float*)sym(g_v_tmp);
    float* v_h    = (float*)sym(g_v_h);
    float* v_node = (float*)sym(g_v_node);
    int* p_indeg  = (int*)sym(g_p_indeg);
    int* v_indeg  = (int*)sym(g_v_indeg);
    float* p_dinv = (float*)sym(g_p_dinv);
    float* v_dinv = (float*)sym(g_v_dinv);
    int* p_csr    = (int*)sym(g_p_csr);
    int* v_csr    = (int*)sym(g_v_csr);
    float* pgp    = (float*)sym(g_pg_part);
    float* vg     = (float*)sym(g_vg);
    float* av     = (float*)sym(g_addvec);

    // ---- graph structure ----
    zero_int<<<(NPG + 255) / 256, 256>>>(p_indeg, NPG);
    zero_int<<<(NVG + 255) / 256, 256>>>(v_indeg, NVG);
    build_csr<<<(EV + 255) / 256, 256>>>(v_src, v_dst, EV, v_indeg, v_csr);
    build_csr<<<(EP + 255) / 256, 256>>>(p_src, p_dst, EP, p_indeg, p_csr);
    compute_dinv<<<(NVG + 255) / 256, 256>>>(v_indeg, v_dinv, NVG);
    compute_dinv<<<(NPG + 255) / 256, 256>>>(p_indeg, p_dinv, NPG);

    // ---- init embeddings ----
    init_emb_kernel<<<NVG, 256>>>(v_x, v_initW, v_initb, v_init, FV);
    init_emb_kernel<<<NPG, 256>>>(p_x, p_initW, p_initb, p_init, FP);

    // ---- v net ----
    {
        dim3 g(2, NVG / 128);
        sgemm256<<<g, 256>>>(v_init, v_W1, v_tmp, NVG);
        gcn_agg<<<(NVG + 7) / 8, 256>>>(v_tmp, v_csr, v_indeg, v_dinv, v_b1, v_h, NVG, 1);
        sgemm256<<<g, 256>>>(v_h, v_W2, v_tmp, NVG);
        gcn_agg<<<(NVG + 7) / 8, 256>>>(v_tmp, v_csr, v_indeg, v_dinv, v_b2, v_node, NVG, 0);
    }
    // ---- p net ----
    {
        dim3 g(2, NPG / 128);
        sgemm256<<<g, 256>>>(p_init, p_W1, p_tmp, NPG);
        gcn_agg<<<(NPG + 7) / 8, 256>>>(p_tmp, p_csr, p_indeg, p_dinv, p_b1, p_h, NPG, 1);
        sgemm256<<<g, 256>>>(p_h, p_W2, p_tmp, NPG);
        gcn_agg<<<(NPG + 7) / 8, 256>>>(p_tmp, p_csr, p_indeg, p_dinv, p_b2, p_node, NPG, 0);
    }

    // ---- pooling + fuse ----
    pool_v_kernel<<<NB, 256>>>(v_node, vg);
    {
        dim3 g(NB, PPOOL);
        pool_p_partial<<<g, 256>>>(p_node, pgp);
    }
    addvec_kernel<<<NB, 256>>>(pgp, vg, v_node, v_init, curr, av);

    const int total4 = NPG * (DD / 4);
    final_kernel<<<(total4 + 255) / 256, 256>>>(p_node, p_init, av, out);
}

// round 5
// speedup vs baseline: 1.1149x; 1.1149x over previous
#include <cuda_runtime.h>
#include <cuda_bf16.h>
#include <cstdint>

// ---------------- problem constants ----------------
#define NB   128
#define NPV  20
#define NPP  500
#define NVG  (NB*NPV)     // 2560
#define NPG  (NB*NPP)     // 64000
#define DD   256
#define FV   6
#define FP   8
#define DEG  8
#define EV   (NVG*DEG)
#define EP   (NPG*DEG)
#define CAP  64
#define PPOOL 10

// ---------------- static device scratch ----------------
__device__ float g_p_init[NPG*DD];
__device__ float g_p_tmp [NPG*DD];
__device__ float g_p_node[NPG*DD];
__device__ __nv_bfloat16 g_p_hi[NPG*DD];
__device__ __nv_bfloat16 g_p_lo[NPG*DD];

__device__ float g_v_init[NVG*DD];
__device__ float g_v_tmp [NVG*DD];
__device__ float g_v_node[NVG*DD];
__device__ __nv_bfloat16 g_v_hi[NVG*DD];
__device__ __nv_bfloat16 g_v_lo[NVG*DD];

// transposed+split weights: Wt[n,k] = W[k,n], [256,256] bf16 hi/lo
__device__ __nv_bfloat16 g_wtv1_hi[DD*DD]; __device__ __nv_bfloat16 g_wtv1_lo[DD*DD];
__device__ __nv_bfloat16 g_wtv2_hi[DD*DD]; __device__ __nv_bfloat16 g_wtv2_lo[DD*DD];
__device__ __nv_bfloat16 g_wtp1_hi[DD*DD]; __device__ __nv_bfloat16 g_wtp1_lo[DD*DD];
__device__ __nv_bfloat16 g_wtp2_hi[DD*DD]; __device__ __nv_bfloat16 g_wtp2_lo[DD*DD];

__device__ int   g_p_indeg[NPG];
__device__ int   g_v_indeg[NVG];
__device__ float g_p_dinv[NPG];
__device__ float g_v_dinv[NVG];
__device__ int   g_p_csr[NPG*CAP];
__device__ int   g_v_csr[NVG*CAP];

__device__ float g_pg_part[NB*PPOOL*DD];
__device__ float g_vg[NB*DD];
__device__ float g_addvec[NB*DD];

// ---------------- basic kernels ----------------
__global__ void zero_int(int* p, int n) {
    int i = blockIdx.x * blockDim.x + threadIdx.x;
    if (i < n) p[i] = 0;
}
__global__ void build_csr(const int* __restrict__ src, const int* __restrict__ dst,
                          int E, int* __restrict__ indeg, int* __restrict__ csr) {
    int e = blockIdx.x * blockDim.x + threadIdx.x;
    if (e >= E) return;
    int d = dst[e];
    int slot = atomicAdd(&indeg[d], 1);
    if (slot < CAP) csr[d * CAP + slot] = src[e];
}
__global__ void compute_dinv(const int* __restrict__ indeg, float* __restrict__ dinv, int n) {
    int i = blockIdx.x * blockDim.x + threadIdx.x;
    if (i < n) dinv[i] = rsqrtf((float)indeg[i] + 1.0f);
}

// transpose + bf16-split weights: Wt[n,k] = W[k,n]
__global__ __launch_bounds__(256) void prep_wt(const float* __restrict__ W,
                                               __nv_bfloat16* __restrict__ hi,
                                               __nv_bfloat16* __restrict__ lo) {
    int n = blockIdx.x, k = threadIdx.x;
    float w = W[k * DD + n];
    __nv_bfloat16 h = __float2bfloat16_rn(w);
    hi[n * DD + k] = h;
    lo[n * DD + k] = __float2bfloat16_rn(w - __bfloat162float(h));
}

// init_emb = x @ W + b ; also emit bf16 hi/lo split
__global__ __launch_bounds__(256) void init_emb_kernel(
    const float* __restrict__ x, const float* __restrict__ W, const float* __restrict__ b,
    float* __restrict__ out, __nv_bfloat16* __restrict__ ohi, __nv_bfloat16* __restrict__ olo,
    int F) {
    int node = blockIdx.x;
    int d = threadIdx.x;
    const float* xr = x + node * F;
    float acc = __ldg(&b[d]);
    #pragma unroll 8
    for (int k = 0; k < 8; k++) {
        if (k < F) acc = fmaf(__ldg(&xr[k]), __ldg(&W[k * DD + d]), acc);
    }
    int idx = node * DD + d;
    out[idx] = acc;
    __nv_bfloat16 h = __float2bfloat16_rn(acc);
    ohi[idx] = h;
    olo[idx] = __float2bfloat16_rn(acc - __bfloat162float(h));
}

// ---------------- mma.sync bf16-split GEMM ----------------
// C[M,256] = A[M,256] @ W[256,256]; A as bf16 hi/lo row-major; W transposed+split
// Wt[n,k] row-major (== B col-major for m16n8k16.row.col).
// CTA tile 128x128 (grid.x=2 covers N=256), 8 warps (4 m x 2 n), warp tile 32x64.
// 3 MMAs per product: hi*hi + hi*lo + lo*hi.
#define MMA_OP(ACC, AH, B0, B1)                                                   \
    asm volatile(                                                                  \
        "mma.sync.aligned.m16n8k16.row.col.f32.bf16.bf16.f32 "                    \
        "{%0,%1,%2,%3}, {%4,%5,%6,%7}, {%8,%9}, {%0,%1,%2,%3};"                   \
        : "+f"((ACC)[0]), "+f"((ACC)[1]), "+f"((ACC)[2]), "+f"((ACC)[3])          \
        : "r"((AH)[0]), "r"((AH)[1]), "r"((AH)[2]), "r"((AH)[3]),                 \
          "r"(B0), "r"(B1))

__global__ __launch_bounds__(256) void gemm_mma(
    const __nv_bfloat16* __restrict__ A_hi, const __nv_bfloat16* __restrict__ A_lo,
    const __nv_bfloat16* __restrict__ Bt_hi, const __nv_bfloat16* __restrict__ Bt_lo,
    float* __restrict__ C) {
    int tid = threadIdx.x;
    int wid = tid >> 5, lane = tid & 31;
    int g = lane >> 2, t = lane & 3;
    int warp_m = wid & 3, warp_n = wid >> 2;
    int row_base = blockIdx.y * 128 + warp_m * 32;
    int col_base = blockIdx.x * 128 + warp_n * 64;

    float acc[2][8][4];
    #pragma unroll
    for (int s = 0; s < 2; s++)
        #pragma unroll
        for (int n = 0; n < 8; n++)
            #pragma unroll
            for (int q = 0; q < 4; q++) acc[s][n][q] = 0.0f;

    for (int kc = 0; kc < DD; kc += 16) {
        uint32_t ah[2][4], al[2][4];
        #pragma unroll
        for (int s = 0; s < 2; s++) {
            int r = row_base + s * 16 + g;
            const char* ph = (const char*)(A_hi + r * DD + kc + t * 2);
            const char* pl = (const char*)(A_lo + r * DD + kc + t * 2);
            ah[s][0] = *(const uint32_t*)ph;
            ah[s][1] = *(const uint32_t*)(ph + 8 * DD * 2);
            ah[s][2] = *(const uint32_t*)(ph + 16);
            ah[s][3] = *(const uint32_t*)(ph + 8 * DD * 2 + 16);
            al[s][0] = *(const uint32_t*)pl;
            al[s][1] = *(const uint32_t*)(pl + 8 * DD * 2);
            al[s][2] = *(const uint32_t*)(pl + 16);
            al[s][3] = *(const uint32_t*)(pl + 8 * DD * 2 + 16);
        }
        #pragma unroll
        for (int nt = 0; nt < 8; nt++) {
            int n = col_base + nt * 8 + g;
            const char* pbh = (const char*)(Bt_hi + n * DD + kc + t * 2);
            const char* pbl = (const char*)(Bt_lo + n * DD + kc + t * 2);
            uint32_t bh0 = *(const uint32_t*)pbh;
            uint32_t bh1 = *(const uint32_t*)(pbh + 16);
            uint32_t bl0 = *(const uint32_t*)pbl;
            uint32_t bl1 = *(const uint32_t*)(pbl + 16);
            #pragma unroll
            for (int s = 0; s < 2; s++) {
                MMA_OP(acc[s][nt], ah[s], bh0, bh1);
                MMA_OP(acc[s][nt], ah[s], bl0, bl1);
                MMA_OP(acc[s][nt], al[s], bh0, bh1);
            }
        }
    }

    // store: lane holds rows (g, g+8), cols t*2..t*2+1 of each 16x8 subtile
    #pragma unroll
    for (int s = 0; s < 2; s++) {
        int r = row_base + s * 16 + g;
        #pragma unroll
        for (int nt = 0; nt < 8; nt++) {
            int c = col_base + nt * 8 + t * 2;
            *(float2*)(C + r * DD + c)        = make_float2(acc[s][nt][0], acc[s][nt][1]);
            *(float2*)(C + (r + 8) * DD + c)  = make_float2(acc[s][nt][2], acc[s][nt][3]);
        }
    }
}

// ---------------- GCN aggregation ----------------
__global__ __launch_bounds__(256) void gcn_agg(
    const float* __restrict__ h, const int* __restrict__ csr, const int* __restrict__ indeg,
    const float* __restrict__ dinv, const float* __restrict__ bias,
    float* __restrict__ out_f32, __nv_bfloat16* __restrict__ out_hi,
    __nv_bfloat16* __restrict__ out_lo, int n_nodes, int do_relu) {
    int warp = threadIdx.x >> 5;
    int lane = threadIdx.x & 31;
    int node = blockIdx.x * 8 + warp;
    if (node >= n_nodes) return;

    int deg = indeg[node];
    int cnt = deg < CAP ? deg : CAP;
    float self = 1.0f / ((float)deg + 1.0f);
    float ddst = dinv[node];
    int d0 = lane * 8;

    const float* hn = h + node * DD + d0;
    float4 s0 = *(const float4*)hn;
    float4 s1 = *(const float4*)(hn + 4);
    float4 acc0 = make_float4(s0.x * self, s0.y * self, s0.z * self, s0.w * self);
    float4 acc1 = make_float4(s1.x * self, s1.y * self, s1.z * self, s1.w * self);

    const int* cp = csr + node * CAP;
    for (int e = 0; e < cnt; e++) {
        int src = cp[e];
        float c = ddst * dinv[src];
        const float* hs = h + src * DD + d0;
        float4 m0 = *(const float4*)hs;
        float4 m1 = *(const float4*)(hs + 4);
        acc0.x = fmaf(c, m0.x, acc0.x); acc0.y = fmaf(c, m0.y, acc0.y);
        acc0.z = fmaf(c, m0.z, acc0.z); acc0.w = fmaf(c, m0.w, acc0.w);
        acc1.x = fmaf(c, m1.x, acc1.x); acc1.y = fmaf(c, m1.y, acc1.y);
        acc1.z = fmaf(c, m1.z, acc1.z); acc1.w = fmaf(c, m1.w, acc1.w);
    }
    float4 b0 = *(const float4*)(bias + d0);
    float4 b1 = *(const float4*)(bias + d0 + 4);
    acc0.x += b0.x; acc0.y += b0.y; acc0.z += b0.z; acc0.w += b0.w;
    acc1.x += b1.x; acc1.y += b1.y; acc1.z += b1.z; acc1.w += b1.w;
    if (do_relu) {
        acc0.x = fmaxf(acc0.x, 0.f); acc0.y = fmaxf(acc0.y, 0.f);
        acc0.z = fmaxf(acc0.z, 0.f); acc0.w = fmaxf(acc0.w, 0.f);
        acc1.x = fmaxf(acc1.x, 0.f); acc1.y = fmaxf(acc1.y, 0.f);
        acc1.z = fmaxf(acc1.z, 0.f); acc1.w = fmaxf(acc1.w, 0.f);
    }
    int base = node * DD + d0;
    if (out_f32) {
        *(float4*)(out_f32 + base) = acc0;
        *(float4*)(out_f32 + base + 4) = acc1;
    }
    if (out_hi) {
        float v[8] = {acc0.x, acc0.y, acc0.z, acc0.w, acc1.x, acc1.y, acc1.z, acc1.w};
        uint32_t hw[4], lw[4];
        #pragma unroll
        for (int q = 0; q < 4; q++) {
            __nv_bfloat16 h0 = __float2bfloat16_rn(v[q * 2]);
            __nv_bfloat16 h1 = __float2bfloat16_rn(v[q * 2 + 1]);
            __nv_bfloat16 l0 = __float2bfloat16_rn(v[q * 2] - __bfloat162float(h0));
            __nv_bfloat16 l1 = __float2bfloat16_rn(v[q * 2 + 1] - __bfloat162float(h1));
            __nv_bfloat162 hp = __nv_bfloat162(h0, h1);
            __nv_bfloat162 lp = __nv_bfloat162(l0, l1);
            hw[q] = *(uint32_t*)&hp;
            lw[q] = *(uint32_t*)&lp;
        }
        *(uint4*)(out_hi + base) = make_uint4(hw[0], hw[1], hw[2], hw[3]);
        *(uint4*)(out_lo + base) = make_uint4(lw[0], lw[1], lw[2], lw[3]);
    }
}

// ---------------- pooling / fuse ----------------
__global__ __launch_bounds__(256) void pool_v_kernel(
    const float* __restrict__ node_emb, float* __restrict__ g) {
    int b = blockIdx.x, d = threadIdx.x;
    const float* p = node_emb + (size_t)b * NPV * DD + d;
    float s = 0.f;
    #pragma unroll
    for (int i = 0; i < NPV; i++) s += p[i * DD];
    g[b * DD + d] = s * (1.0f / NPV);
}
__global__ __launch_bounds__(256) void pool_p_partial(
    const float* __restrict__ node_emb, float* __restrict__ part) {
    int b = blockIdx.x, ppart = blockIdx.y, d = threadIdx.x;
    const int chunk = NPP / PPOOL;
    const float* p = node_emb + ((size_t)b * NPP + ppart * chunk) * DD + d;
    float s0 = 0.f, s1 = 0.f;
    #pragma unroll
    for (int i = 0; i < chunk; i += 2) {
        s0 += p[i * DD];
        s1 += p[(i + 1) * DD];
    }
    part[(b * PPOOL + ppart) * DD + d] = s0 + s1;
}
__global__ void addvec_kernel(const float* __restrict__ pg_part, const float* __restrict__ vg,
                              const float* __restrict__ v_node, const float* __restrict__ v_init,
                              const int* __restrict__ curr, float* __restrict__ av) {
    int b = blockIdx.x, d = threadIdx.x;
    float pgs = 0.f;
    #pragma unroll
    for (int j = 0; j < PPOOL; j++) pgs += pg_part[(b * PPOOL + j) * DD + d];
    float pgd = pgs * (1.0f / NPP);
    int cid = curr[b];
    int vi = (b * NPV + cid) * DD + d;
    av[b * DD + d] = pgd + 2.0f * vg[b * DD + d] + v_node[vi] + v_init[vi];
}
__global__ void final_kernel(const float* __restrict__ pn, const float* __restrict__ pi,
                             const float* __restrict__ av, float* __restrict__ out) {
    int idx = blockIdx.x * blockDim.x + threadIdx.x;
    const int total4 = NPG * (DD / 4);
    if (idx >= total4) return;
    int node = idx >> 6;
    int d4 = idx & 63;
    int b = node / NPP;
    float4 a = ((const float4*)pn)[idx];
    float4 c = ((const float4*)pi)[idx];
    float4 v = ((const float4*)av)[b * (DD / 4) + d4];
    ((float4*)out)[idx] = make_float4(a.x + c.x + v.x, a.y + c.y + v.y,
                                      a.z + c.z + v.z, a.w + c.w + v.w);
}

// ---------------- host launch ----------------
static inline void* sym(const void* s) {
    void* p = nullptr;
    cudaGetSymbolAddress(&p, s);
    return p;
}

extern "C" void kernel_launch(void* const* d_in, const int* in_sizes, int n_in,
                              void* d_out, int out_size) {
    const float* v_x     = (const float*)d_in[0];
    const float* p_x     = (const float*)d_in[1];
    const int*   v_src   = (const int*)d_in[2];
    const int*   v_dst   = (const int*)d_in[3];
    const int*   p_src   = (const int*)d_in[4];
    const int*   p_dst   = (const int*)d_in[5];
    const int*   curr    = (const int*)d_in[8];
    const float* v_initW = (const float*)d_in[9];
    const float* v_initb = (const float*)d_in[10];
    const float* v_W1    = (const float*)d_in[11];
    const float* v_b1    = (const float*)d_in[12];
    const float* v_W2    = (const float*)d_in[13];
    const float* v_b2    = (const float*)d_in[14];
    const float* p_initW = (const float*)d_in[15];
    const float* p_initb = (const float*)d_in[16];
    const float* p_W1    = (const float*)d_in[17];
    const float* p_b1    = (const float*)d_in[18];
    const float* p_W2    = (const float*)d_in[19];
    const float* p_b2    = (const float*)d_in[20];
    float* out = (float*)d_out;

    float* p_init = (float*)sym(g_p_init);
    float* p_tmp  = (float*)sym(g_p_tmp);
    float* p_node = (float*)sym(g_p_node);
    __nv_bfloat16* p_hi = (__nv_bfloat16*)sym(g_p_hi);
    __nv_bfloat16* p_lo = (__nv_bfloat16*)sym(g_p_lo);
    float* v_init = (float*)sym(g_v_init);
    float* v_tmp  = (float*)sym(g_v_tmp);
    float* v_node = (float*)sym(g_v_node);
    __nv_bfloat16* v_hi = (__nv_bfloat16*)sym(g_v_hi);
    __nv_bfloat16* v_lo = (__nv_bfloat16*)sym(g_v_lo);

    __nv_bfloat16* wtv1h = (__nv_bfloat16*)sym(g_wtv1_hi); __nv_bfloat16* wtv1l = (__nv_bfloat16*)sym(g_wtv1_lo);
    __nv_bfloat16* wtv2h = (__nv_bfloat16*)sym(g_wtv2_hi); __nv_bfloat16* wtv2l = (__nv_bfloat16*)sym(g_wtv2_lo);
    __nv_bfloat16* wtp1h = (__nv_bfloat16*)sym(g_wtp1_hi); __nv_bfloat16* wtp1l = (__nv_bfloat16*)sym(g_wtp1_lo);
    __nv_bfloat16* wtp2h = (__nv_bfloat16*)sym(g_wtp2_hi); __nv_bfloat16* wtp2l = (__nv_bfloat16*)sym(g_wtp2_lo);

    int* p_indeg  = (int*)sym(g_p_indeg);
    int* v_indeg  = (int*)sym(g_v_indeg);
    float* p_dinv = (float*)sym(g_p_dinv);
    float* v_dinv = (float*)sym(g_v_dinv);
    int* p_csr    = (int*)sym(g_p_csr);
    int* v_csr    = (int*)sym(g_v_csr);
    float* pgp    = (float*)sym(g_pg_part);
    float* vg     = (float*)sym(g_vg);
    float* av     = (float*)sym(g_addvec);

    // ---- graph structure ----
    zero_int<<<(NPG + 255) / 256, 256>>>(p_indeg, NPG);
    zero_int<<<(NVG + 255) / 256, 256>>>(v_indeg, NVG);
    build_csr<<<(EV + 255) / 256, 256>>>(v_src, v_dst, EV, v_indeg, v_csr);
    build_csr<<<(EP + 255) / 256, 256>>>(p_src, p_dst, EP, p_indeg, p_csr);
    compute_dinv<<<(NVG + 255) / 256, 256>>>(v_indeg, v_dinv, NVG);
    compute_dinv<<<(NPG + 255) / 256, 256>>>(p_indeg, p_dinv, NPG);

    // ---- weight prep (transpose + bf16 split) ----
    prep_wt<<<DD, 256>>>(v_W1, wtv1h, wtv1l);
    prep_wt<<<DD, 256>>>(v_W2, wtv2h, wtv2l);
    prep_wt<<<DD, 256>>>(p_W1, wtp1h, wtp1l);
    prep_wt<<<DD, 256>>>(p_W2, wtp2h, wtp2l);

    // ---- init embeddings (fp32 + split) ----
    init_emb_kernel<<<NVG, 256>>>(v_x, v_initW, v_initb, v_init, v_hi, v_lo, FV);
    init_emb_kernel<<<NPG, 256>>>(p_x, p_initW, p_initb, p_init, p_hi, p_lo, FP);

    // ---- v net ----
    {
        dim3 gv(2, NVG / 128);
        gemm_mma<<<gv, 256>>>(v_hi, v_lo, wtv1h, wtv1l, v_tmp);
        gcn_agg<<<(NVG + 7) / 8, 256>>>(v_tmp, v_csr, v_indeg, v_dinv, v_b1,
                                        nullptr, v_hi, v_lo, NVG, 1);
        gemm_mma<<<gv, 256>>>(v_hi, v_lo, wtv2h, wtv2l, v_tmp);
        gcn_agg<<<(NVG + 7) / 8, 256>>>(v_tmp, v_csr, v_indeg, v_dinv, v_b2,
                                        v_node, nullptr, nullptr, NVG, 0);
    }
    // ---- p net ----
    {
        dim3 gp(2, NPG / 128);
        gemm_mma<<<gp, 256>>>(p_hi, p_lo, wtp1h, wtp1l, p_tmp);
        gcn_agg<<<(NPG + 7) / 8, 256>>>(p_tmp, p_csr, p_indeg, p_dinv, p_b1,
                                        nullptr, p_hi, p_lo, NPG, 1);
        gemm_mma<<<gp, 256>>>(p_hi, p_lo, wtp2h, wtp2l, p_tmp);
        gcn_agg<<<(NPG + 7) / 8, 256>>>(p_tmp, p_csr, p_indeg, p_dinv, p_b2,
                                        p_node, nullptr, nullptr, NPG, 0);
    }

    // ---- pooling + fuse ----
    pool_v_kernel<<<NB, 256>>>(v_node, vg);
    {
        dim3 g(NB, PPOOL);
        pool_p_partial<<<g, 256>>>(p_node, pgp);
    }
    addvec_kernel<<<NB, 256>>>(pgp, vg, v_node, v_init, curr, av);

    const int total4 = NPG * (DD / 4);
    final_kernel<<<(total4 + 255) / 256, 256>>>(p_node, p_init, av, out);
}

// round 7
// speedup vs baseline: 2.3151x; 2.0766x over previous
#include <cuda_runtime.h>
#include <cuda_bf16.h>
#include <cstdint>

// ---------------- problem constants ----------------
#define NB   128
#define NPV  20
#define NPP  500
#define NVG  (NB*NPV)     // 2560
#define NPG  (NB*NPP)     // 64000
#define DD   256
#define FV   6
#define FP   8
#define DEG  8
#define EV   (NVG*DEG)
#define EP   (NPG*DEG)
#define CAP  64
#define PPOOL 10

// ---------------- static device scratch ----------------
__device__ float g_p_tmp [NPG*DD];            // h1 (layer-1 output)
__device__ float g_p_node[NPG*DD];            // layer-2 output
__device__ __nv_bfloat16 g_p_hi[NPG*DD];      // agg(h1) split
__device__ __nv_bfloat16 g_p_lo[NPG*DD];

__device__ float g_v_init[NVG*DD];
__device__ float g_v_tmp [NVG*DD];
__device__ float g_v_node[NVG*DD];
__device__ __nv_bfloat16 g_v_hi[NVG*DD];
__device__ __nv_bfloat16 g_v_lo[NVG*DD];

__device__ __nv_bfloat16 g_wtv2_hi[DD*DD]; __device__ __nv_bfloat16 g_wtv2_lo[DD*DD];
__device__ __nv_bfloat16 g_wtp2_hi[DD*DD]; __device__ __nv_bfloat16 g_wtp2_lo[DD*DD];

__device__ float g_Mp[9*DD];   // rows 0-7: Wi@W1 (zero-padded); row 8: bi@W1
__device__ float g_Mv[9*DD];

__device__ float g_p_agg8[NPG*8];
__device__ float g_p_s[NPG];
__device__ float g_v_agg8[NVG*8];
__device__ float g_v_s[NVG];

__device__ int   g_p_indeg[NPG];
__device__ int   g_v_indeg[NVG];
__device__ float g_p_dinv[NPG];
__device__ float g_v_dinv[NVG];
__device__ int   g_p_csr[NPG*CAP];
__device__ int   g_v_csr[NVG*CAP];

__device__ float g_pg_part[NB*PPOOL*DD];
__device__ float g_vg[NB*DD];
__device__ float g_addvec[NB*DD];

// ---------------- helpers ----------------
__device__ __forceinline__ uint32_t smem_u32(const void* p) {
    uint32_t a;
    asm("{ .reg .u64 t; cvta.to.shared.u64 t, %1; cvt.u32.u64 %0, t; }" : "=r"(a) : "l"(p));
    return a;
}
__device__ __forceinline__ void cpa16(uint32_t dst, const void* src) {
    asm volatile("cp.async.cg.shared.global [%0], [%1], 16;" :: "r"(dst), "l"(src) : "memory");
}
#define CPA_COMMIT() asm volatile("cp.async.commit_group;" ::: "memory")
#define CPA_WAIT0()  asm volatile("cp.async.wait_group 0;" ::: "memory")

#define MMA_OP(ACC, AH, B0, B1)                                                   \
    asm volatile(                                                                  \
        "mma.sync.aligned.m16n8k16.row.col.f32.bf16.bf16.f32 "                    \
        "{%0,%1,%2,%3}, {%4,%5,%6,%7}, {%8,%9}, {%0,%1,%2,%3};"                   \
        : "+f"((ACC)[0]), "+f"((ACC)[1]), "+f"((ACC)[2]), "+f"((ACC)[3])          \
        : "r"((AH)[0]), "r"((AH)[1]), "r"((AH)[2]), "r"((AH)[3]),                 \
          "r"(B0), "r"(B1))

// ---------------- graph structure ----------------
__global__ void zero_int(int* p, int n) {
    int i = blockIdx.x * blockDim.x + threadIdx.x;
    if (i < n) p[i] = 0;
}
__global__ void build_csr(const int* __restrict__ src, const int* __restrict__ dst,
                          int E, int* __restrict__ indeg, int* __restrict__ csr) {
    int e = blockIdx.x * blockDim.x + threadIdx.x;
    if (e >= E) return;
    int d = dst[e];
    int slot = atomicAdd(&indeg[d], 1);
    if (slot < CAP) csr[d * CAP + slot] = src[e];
}
__global__ void compute_dinv(const int* __restrict__ indeg, float* __restrict__ dinv, int n) {
    int i = blockIdx.x * blockDim.x + threadIdx.x;
    if (i < n) dinv[i] = rsqrtf((float)indeg[i] + 1.0f);
}

// ---------------- weight prep ----------------
// M rows 0..7 = Wi@W1 (row f zero for f>=F); row 8 = bi@W1
__global__ __launch_bounds__(256) void prep_M(
    const float* __restrict__ Wi, const float* __restrict__ bi,
    const float* __restrict__ W1, float* __restrict__ M, int F) {
    int f = blockIdx.x, d = threadIdx.x;
    float acc = 0.0f;
    if (f < 8) {
        if (f < F) {
            for (int j = 0; j < DD; j++)
                acc = fmaf(__ldg(&Wi[f * DD + j]), __ldg(&W1[j * DD + d]), acc);
        }
    } else {
        for (int j = 0; j < DD; j++)
            acc = fmaf(__ldg(&bi[j]), __ldg(&W1[j * DD + d]), acc);
    }
    M[f * DD + d] = acc;
}

// transpose + bf16 split: Wt[n,k] = W[k,n]
__global__ __launch_bounds__(256) void prep_wt(const float* __restrict__ W,
                                               __nv_bfloat16* __restrict__ hi,
                                               __nv_bfloat16* __restrict__ lo) {
    int n = blockIdx.x, k = threadIdx.x;
    float w = W[k * DD + n];
    __nv_bfloat16 h = __float2bfloat16_rn(w);
    hi[n * DD + k] = h;
    lo[n * DD + k] = __float2bfloat16_rn(w - __bfloat162float(h));
}

// init_emb = x @ Wi + bi (f32 only; v-net only)
__global__ __launch_bounds__(256) void init_emb_kernel(
    const float* __restrict__ x, const float* __restrict__ W, const float* __restrict__ b,
    float* __restrict__ out, int F) {
    int node = blockIdx.x, d = threadIdx.x;
    const float* xr = x + node * F;
    float acc = __ldg(&b[d]);
    #pragma unroll 8
    for (int k = 0; k < 8; k++)
        if (k < F) acc = fmaf(__ldg(&xr[k]), __ldg(&W[k * DD + d]), acc);
    out[node * DD + d] = acc;
}

// ---------------- feature-space aggregation (layer 1) ----------------
// agg8[i,f] = x[i,f]/deg + sum_in dinv[src]*dinv[i]*x[src,f];  s[i] = 1/deg + sum_in coef
__global__ __launch_bounds__(256) void agg8_s_kernel(
    const float* __restrict__ x, const int* __restrict__ csr, const int* __restrict__ indeg,
    const float* __restrict__ dinv, float* __restrict__ agg8, float* __restrict__ sv,
    int n_nodes, int F) {
    int node = blockIdx.x * blockDim.x + threadIdx.x;
    if (node >= n_nodes) return;
    int deg = indeg[node];
    int cnt = deg < CAP ? deg : CAP;
    float self = 1.0f / ((float)deg + 1.0f);
    float ddst = dinv[node];
    float a[8];
    #pragma unroll
    for (int f = 0; f < 8; f++) a[f] = 0.0f;
    if (F == 8) {
        float4 x0 = *(const float4*)(x + node * 8);
        float4 x1 = *(const float4*)(x + node * 8 + 4);
        a[0] = x0.x * self; a[1] = x0.y * self; a[2] = x0.z * self; a[3] = x0.w * self;
        a[4] = x1.x * self; a[5] = x1.y * self; a[6] = x1.z * self; a[7] = x1.w * self;
    } else {
        for (int f = 0; f < F; f++) a[f] = x[node * F + f] * self;
    }
    float ssum = self;
    const int* cp = csr + node * CAP;
    for (int e = 0; e < cnt; e++) {
        int src = cp[e];
        float c = ddst * dinv[src];
        ssum += c;
        if (F == 8) {
            float4 m0 = *(const float4*)(x + src * 8);
            float4 m1 = *(const float4*)(x + src * 8 + 4);
            a[0] = fmaf(c, m0.x, a[0]); a[1] = fmaf(c, m0.y, a[1]);
            a[2] = fmaf(c, m0.z, a[2]); a[3] = fmaf(c, m0.w, a[3]);
            a[4] = fmaf(c, m1.x, a[4]); a[5] = fmaf(c, m1.y, a[5]);
            a[6] = fmaf(c, m1.z, a[6]); a[7] = fmaf(c, m1.w, a[7]);
        } else {
            for (int f = 0; f < F; f++) a[f] = fmaf(c, x[src * F + f], a[f]);
        }
    }
    *(float4*)(agg8 + node * 8)     = make_float4(a[0], a[1], a[2], a[3]);
    *(float4*)(agg8 + node * 8 + 4) = make_float4(a[4], a[5], a[6], a[7]);
    sv[node] = ssum;
}

// h1 = relu(agg8 @ M[0:8] + s * M[8] + b1)
__global__ __launch_bounds__(256) void layer1_combine(
    const float* __restrict__ agg8, const float* __restrict__ sv,
    const float* __restrict__ M, const float* __restrict__ b1,
    float* __restrict__ h1) {
    int node = blockIdx.x, d = threadIdx.x;
    __shared__ float a[8];
    __shared__ float ss;
    if (threadIdx.x < 8) a[threadIdx.x] = agg8[node * 8 + threadIdx.x];
    if (threadIdx.x == 8) ss = sv[node];
    __syncthreads();
    float acc = __ldg(&b1[d]) + ss * __ldg(&M[8 * DD + d]);
    #pragma unroll
    for (int k = 0; k < 8; k++)
        acc = fmaf(a[k], __ldg(&M[k * DD + d]), acc);
    h1[node * DD + d] = fmaxf(acc, 0.0f);
}

// ---------------- 256-dim aggregation (layer 2 input) ----------------
// out = h[node]/deg + sum_in h[src]*coef  (+optional bias/relu); f32 and/or hi/lo outputs
__global__ __launch_bounds__(256) void gcn_agg(
    const float* __restrict__ h, const int* __restrict__ csr, const int* __restrict__ indeg,
    const float* __restrict__ dinv, const float* __restrict__ bias,
    float* __restrict__ out_f32, __nv_bfloat16* __restrict__ out_hi,
    __nv_bfloat16* __restrict__ out_lo, int n_nodes, int do_relu) {
    int warp = threadIdx.x >> 5;
    int lane = threadIdx.x & 31;
    int node = blockIdx.x * 8 + warp;
    if (node >= n_nodes) return;

    int deg = indeg[node];
    int cnt = deg < CAP ? deg : CAP;
    float self = 1.0f / ((float)deg + 1.0f);
    float ddst = dinv[node];
    int d0 = lane * 8;

    const float* hn = h + node * DD + d0;
    float4 s0 = *(const float4*)hn;
    float4 s1 = *(const float4*)(hn + 4);
    float4 acc0 = make_float4(s0.x * self, s0.y * self, s0.z * self, s0.w * self);
    float4 acc1 = make_float4(s1.x * self, s1.y * self, s1.z * self, s1.w * self);

    const int* cp = csr + node * CAP;
    for (int e = 0; e < cnt; e++) {
        int src = cp[e];
        float c = ddst * dinv[src];
        const float* hs = h + src * DD + d0;
        float4 m0 = *(const float4*)hs;
        float4 m1 = *(const float4*)(hs + 4);
        acc0.x = fmaf(c, m0.x, acc0.x); acc0.y = fmaf(c, m0.y, acc0.y);
        acc0.z = fmaf(c, m0.z, acc0.z); acc0.w = fmaf(c, m0.w, acc0.w);
        acc1.x = fmaf(c, m1.x, acc1.x); acc1.y = fmaf(c, m1.y, acc1.y);
        acc1.z = fmaf(c, m1.z, acc1.z); acc1.w = fmaf(c, m1.w, acc1.w);
    }
    if (bias) {
        float4 b0 = *(const float4*)(bias + d0);
        float4 b1 = *(const float4*)(bias + d0 + 4);
        acc0.x += b0.x; acc0.y += b0.y; acc0.z += b0.z; acc0.w += b0.w;
        acc1.x += b1.x; acc1.y += b1.y; acc1.z += b1.z; acc1.w += b1.w;
    }
    if (do_relu) {
        acc0.x = fmaxf(acc0.x, 0.f); acc0.y = fmaxf(acc0.y, 0.f);
        acc0.z = fmaxf(acc0.z, 0.f); acc0.w = fmaxf(acc0.w, 0.f);
        acc1.x = fmaxf(acc1.x, 0.f); acc1.y = fmaxf(acc1.y, 0.f);
        acc1.z = fmaxf(acc1.z, 0.f); acc1.w = fmaxf(acc1.w, 0.f);
    }
    int base = node * DD + d0;
    if (out_f32) {
        *(float4*)(out_f32 + base) = acc0;
        *(float4*)(out_f32 + base + 4) = acc1;
    }
    if (out_hi) {
        float v[8] = {acc0.x, acc0.y, acc0.z, acc0.w, acc1.x, acc1.y, acc1.z, acc1.w};
        uint32_t hw[4], lw[4];
        #pragma unroll
        for (int q = 0; q < 4; q++) {
            __nv_bfloat16 h0 = __float2bfloat16_rn(v[q * 2]);
            __nv_bfloat16 h1v = __float2bfloat16_rn(v[q * 2 + 1]);
            __nv_bfloat16 l0 = __float2bfloat16_rn(v[q * 2] - __bfloat162float(h0));
            __nv_bfloat16 l1 = __float2bfloat16_rn(v[q * 2 + 1] - __bfloat162float(h1v));
            __nv_bfloat162 hp = __nv_bfloat162(h0, h1v);
            __nv_bfloat162 lp = __nv_bfloat162(l0, l1);
            hw[q] = *(uint32_t*)&hp;
            lw[q] = *(uint32_t*)&lp;
        }
        *(uint4*)(out_hi + base) = make_uint4(hw[0], hw[1], hw[2], hw[3]);
        *(uint4*)(out_lo + base) = make_uint4(lw[0], lw[1], lw[2], lw[3]);
    }
}

// ---------------- smem-staged bf16-split GEMM ----------------
// C[M,256] = A[M,256] @ W + bias; A = hi/lo row-major; W transposed+split (Bt[n,k]).
// grid (2, M/128); CTA 128x128; 8 warps (4m x 2n); warp 32x64; KC=32, 8 stages,
// cp.async double buffer. 3 MMAs per product (hh+hl+lh).
#define KC 32
#define APITCH 80                 // 64B data + 16B pad per row
#define PIECE (128*APITCH)        // 10240
#define STAGE_BYTES (4*PIECE)     // 40960
#define GEMM_SMEM (2*STAGE_BYTES) // 81920

__global__ void __launch_bounds__(256, 2) gemm_smem(
    const __nv_bfloat16* __restrict__ A_hi, const __nv_bfloat16* __restrict__ A_lo,
    const __nv_bfloat16* __restrict__ Bt_hi, const __nv_bfloat16* __restrict__ Bt_lo,
    const float* __restrict__ bias, float* __restrict__ C) {
    extern __shared__ char sm[];
    uint32_t sb = smem_u32(sm);
    int tid = threadIdx.x;
    int wid = tid >> 5, lane = tid & 31;
    int g = lane >> 2, t = lane & 3;
    int warp_m = wid & 3, warp_n = wid >> 2;
    int row0 = blockIdx.y * 128;
    int col0 = blockIdx.x * 128;

    float acc[2][8][4];
    #pragma unroll
    for (int s = 0; s < 2; s++)
        #pragma unroll
        for (int n = 0; n < 8; n++)
            #pragma unroll
            for (int q = 0; q < 4; q++) acc[s][n][q] = 0.0f;

    // per-thread load coords (2 uint4 per piece)
    int r0i = (tid + 0) >> 2,  c0i = (tid + 0) & 3;
    int r1i = (tid + 256) >> 2, c1i = (tid + 256) & 3;

    auto stage_load = [&](int st) {
        uint32_t base = sb + (st & 1) * STAGE_BYTES;
        int kc0 = st * KC;
        {
            uint32_t d0 = base + r0i * APITCH + c0i * 16;
            size_t ga = (size_t)(row0 + r0i) * DD + kc0 + c0i * 8;
            size_t gb = (size_t)(col0 + r0i) * DD + kc0 + c0i * 8;
            cpa16(d0,             A_hi + ga);
            cpa16(d0 + PIECE,     A_lo + ga);
            cpa16(d0 + 2*PIECE,   Bt_hi + gb);
            cpa16(d0 + 3*PIECE,   Bt_lo + gb);
        }
        {
            uint32_t d0 = base + r1i * APITCH + c1i * 16;
            size_t ga = (size_t)(row0 + r1i) * DD + kc0 + c1i * 8;
            size_t gb = (size_t)(col0 + r1i) * DD + kc0 + c1i * 8;
            cpa16(d0,             A_hi + ga);
            cpa16(d0 + PIECE,     A_lo + ga);
            cpa16(d0 + 2*PIECE,   Bt_hi + gb);
            cpa16(d0 + 3*PIECE,   Bt_lo + gb);
        }
        CPA_COMMIT();
    };

    stage_load(0);
    CPA_WAIT0();
    __syncthreads();

    for (int st = 0; st < DD / KC; st++) {
        if (st + 1 < DD / KC) stage_load(st + 1);
        const char* cur = sm + (st & 1) * STAGE_BYTES;

        #pragma unroll
        for (int kk = 0; kk < 2; kk++) {
            int kb = (kk * 16 + t * 2) * 2;     // byte col within 64B row
            uint32_t ah[2][4], al[2][4];
            #pragma unroll
            for (int s = 0; s < 2; s++) {
                const char* pa = cur + (warp_m * 32 + s * 16 + g) * APITCH + kb;
                ah[s][0] = *(const uint32_t*)pa;
                ah[s][1] = *(const uint32_t*)(pa + 8 * APITCH);
                ah[s][2] = *(const uint32_t*)(pa + 16);
                ah[s][3] = *(const uint32_t*)(pa + 8 * APITCH + 16);
                const char* pl = pa + PIECE;
                al[s][0] = *(const uint32_t*)pl;
                al[s][1] = *(const uint32_t*)(pl + 8 * APITCH);
                al[s][2] = *(const uint32_t*)(pl + 16);
                al[s][3] = *(const uint32_t*)(pl + 8 * APITCH + 16);
            }
            #pragma unroll
            for (int nt = 0; nt < 8; nt++) {
                const char* pb = cur + 2 * PIECE + (warp_n * 64 + nt * 8 + g) * APITCH + kb;
                uint32_t bh0 = *(const uint32_t*)pb;
                uint32_t bh1 = *(const uint32_t*)(pb + 16);
                const char* pbl = pb + PIECE;
                uint32_t bl0 = *(const uint32_t*)pbl;
                uint32_t bl1 = *(const uint32_t*)(pbl + 16);
                #pragma unroll
                for (int s = 0; s < 2; s++) {
                    MMA_OP(acc[s][nt], ah[s], bh0, bh1);
                    MMA_OP(acc[s][nt], ah[s], bl0, bl1);
                    MMA_OP(acc[s][nt], al[s], bh0, bh1);
                }
            }
        }
        CPA_WAIT0();
        __syncthreads();
    }

    // epilogue: + bias, store
    #pragma unroll
    for (int s = 0; s < 2; s++) {
        int r = row0 + warp_m * 32 + s * 16 + g;
        #pragma unroll
        for (int nt = 0; nt < 8; nt++) {
            int c = col0 + warp_n * 64 + nt * 8 + t * 2;
            float bx = __ldg(&bias[c]), by = __ldg(&bias[c + 1]);
            *(float2*)(C + r * DD + c)       = make_float2(acc[s][nt][0] + bx, acc[s][nt][1] + by);
            *(float2*)(C + (r + 8) * DD + c) = make_float2(acc[s][nt][2] + bx, acc[s][nt][3] + by);
        }
    }
}

// ---------------- pooling / fuse ----------------
__global__ __launch_bounds__(256) void pool_v_kernel(
    const float* __restrict__ node_emb, float* __restrict__ g) {
    int b = blockIdx.x, d = threadIdx.x;
    const float* p = node_emb + (size_t)b * NPV * DD + d;
    float s = 0.f;
    #pragma unroll
    for (int i = 0; i < NPV; i++) s += p[i * DD];
    g[b * DD + d] = s * (1.0f / NPV);
}
__global__ __launch_bounds__(256) void pool_p_partial(
    const float* __restrict__ node_emb, float* __restrict__ part) {
    int b = blockIdx.x, ppart = blockIdx.y, d = threadIdx.x;
    const int chunk = NPP / PPOOL;
    const float* p = node_emb + ((size_t)b * NPP + ppart * chunk) * DD + d;
    float s0 = 0.f, s1 = 0.f;
    #pragma unroll
    for (int i = 0; i < chunk; i += 2) {
        s0 += p[i * DD];
        s1 += p[(i + 1) * DD];
    }
    part[(b * PPOOL + ppart) * DD + d] = s0 + s1;
}
__global__ void addvec_kernel(const float* __restrict__ pg_part, const float* __restrict__ vg,
                              const float* __restrict__ v_node, const float* __restrict__ v_init,
                              const int* __restrict__ curr, float* __restrict__ av) {
    int b = blockIdx.x, d = threadIdx.x;
    float pgs = 0.f;
    #pragma unroll
    for (int j = 0; j < PPOOL; j++) pgs += pg_part[(b * PPOOL + j) * DD + d];
    float pgd = pgs * (1.0f / NPP);
    int cid = curr[b];
    int vi = (b * NPV + cid) * DD + d;
    av[b * DD + d] = pgd + 2.0f * vg[b * DD + d] + v_node[vi] + v_init[vi];
}

// out = p_node + (p_x@Wi + bi) + addvec[b]   (p_init recomputed on the fly)
__global__ void final_kernel(const float* __restrict__ pn, const float* __restrict__ px,
                             const float* __restrict__ Wi, const float* __restrict__ bi,
                             const float* __restrict__ av, float* __restrict__ out) {
    int idx = blockIdx.x * blockDim.x + threadIdx.x;   // float4 index
    const int total4 = NPG * (DD / 4);
    if (idx >= total4) return;
    int node = idx >> 6;
    int d4 = idx & 63;
    int d = d4 * 4;
    int b = node / NPP;
    float4 a = ((const float4*)pn)[idx];
    float4 v = ((const float4*)av)[b * (DD / 4) + d4];
    float4 bb = *(const float4*)(bi + d);
    float4 r = make_float4(a.x + v.x + bb.x, a.y + v.y + bb.y,
                           a.z + v.z + bb.z, a.w + v.w + bb.w);
    const float* xr = px + node * FP;
    #pragma unroll
    for (int k = 0; k < FP; k++) {
        float xv = __ldg(&xr[k]);
        float4 w = *(const float4*)(Wi + k * DD + d);
        r.x = fmaf(xv, w.x, r.x); r.y = fmaf(xv, w.y, r.y);
        r.z = fmaf(xv, w.z, r.z); r.w = fmaf(xv, w.w, r.w);
    }
    ((float4*)out)[idx] = r;
}

// ---------------- host launch ----------------
static inline void* sym(const void* s) {
    void* p = nullptr;
    cudaGetSymbolAddress(&p, s);
    return p;
}

extern "C" void kernel_launch(void* const* d_in, const int* in_sizes, int n_in,
                              void* d_out, int out_size) {
    const float* v_x     = (const float*)d_in[0];
    const float* p_x     = (const float*)d_in[1];
    const int*   v_src   = (const int*)d_in[2];
    const int*   v_dst   = (const int*)d_in[3];
    const int*   p_src   = (const int*)d_in[4];
    const int*   p_dst   = (const int*)d_in[5];
    const int*   curr    = (const int*)d_in[8];
    const float* v_initW = (const float*)d_in[9];
    const float* v_initb = (const float*)d_in[10];
    const float* v_W1    = (const float*)d_in[11];
    const float* v_b1    = (const float*)d_in[12];
    const float* v_W2    = (const float*)d_in[13];
    const float* v_b2    = (const float*)d_in[14];
    const float* p_initW = (const float*)d_in[15];
    const float* p_initb = (const float*)d_in[16];
    const float* p_W1    = (const float*)d_in[17];
    const float* p_b1    = (const float*)d_in[18];
    const float* p_W2    = (const float*)d_in[19];
    const float* p_b2    = (const float*)d_in[20];
    float* out = (float*)d_out;

    float* p_tmp  = (float*)sym(g_p_tmp);
    float* p_node = (float*)sym(g_p_node);
    __nv_bfloat16* p_hi = (__nv_bfloat16*)sym(g_p_hi);
    __nv_bfloat16* p_lo = (__nv_bfloat16*)sym(g_p_lo);
    float* v_init = (float*)sym(g_v_init);
    float* v_tmp  = (float*)sym(g_v_tmp);
    float* v_node = (float*)sym(g_v_node);
    __nv_bfloat16* v_hi = (__nv_bfloat16*)sym(g_v_hi);
    __nv_bfloat16* v_lo = (__nv_bfloat16*)sym(g_v_lo);
    __nv_bfloat16* wtv2h = (__nv_bfloat16*)sym(g_wtv2_hi);
    __nv_bfloat16* wtv2l = (__nv_bfloat16*)sym(g_wtv2_lo);
    __nv_bfloat16* wtp2h = (__nv_bfloat16*)sym(g_wtp2_hi);
    __nv_bfloat16* wtp2l = (__nv_bfloat16*)sym(g_wtp2_lo);
    float* Mp = (float*)sym(g_Mp);
    float* Mv = (float*)sym(g_Mv);
    float* p_agg8 = (float*)sym(g_p_agg8);
    float* p_s    = (float*)sym(g_p_s);
    float* v_agg8 = (float*)sym(g_v_agg8);
    float* v_s    = (float*)sym(g_v_s);
    int* p_indeg  = (int*)sym(g_p_indeg);
    int* v_indeg  = (int*)sym(g_v_indeg);
    float* p_dinv = (float*)sym(g_p_dinv);
    float* v_dinv = (float*)sym(g_v_dinv);
    int* p_csr    = (int*)sym(g_p_csr);
    int* v_csr    = (int*)sym(g_v_csr);
    float* pgp    = (float*)sym(g_pg_part);
    float* vg     = (float*)sym(g_vg);
    float* av     = (float*)sym(g_addvec);

    cudaFuncSetAttribute(gemm_smem, cudaFuncAttributeMaxDynamicSharedMemorySize, GEMM_SMEM);

    // ---- graph structure ----
    zero_int<<<(NPG + 255) / 256, 256>>>(p_indeg, NPG);
    zero_int<<<(NVG + 255) / 256, 256>>>(v_indeg, NVG);
    build_csr<<<(EV + 255) / 256, 256>>>(v_src, v_dst, EV, v_indeg, v_csr);
    build_csr<<<(EP + 255) / 256, 256>>>(p_src, p_dst, EP, p_indeg, p_csr);
    compute_dinv<<<(NVG + 255) / 256, 256>>>(v_indeg, v_dinv, NVG);
    compute_dinv<<<(NPG + 255) / 256, 256>>>(p_indeg, p_dinv, NPG);

    // ---- weight prep ----
    prep_M<<<9, 256>>>(p_initW, p_initb, p_W1, Mp, FP);
    prep_M<<<9, 256>>>(v_initW, v_initb, v_W1, Mv, FV);
    prep_wt<<<DD, 256>>>(p_W2, wtp2h, wtp2l);
    prep_wt<<<DD, 256>>>(v_W2, wtv2h, wtv2l);

    // ---- v init emb (needed in addvec) ----
    init_emb_kernel<<<NVG, 256>>>(v_x, v_initW, v_initb, v_init, FV);

    // ---- layer 1 (feature-space agg + combine) ----
    agg8_s_kernel<<<(NPG + 255) / 256, 256>>>(p_x, p_csr, p_indeg, p_dinv, p_agg8, p_s, NPG, FP);
    agg8_s_kernel<<<(NVG + 255) / 256, 256>>>(v_x, v_csr, v_indeg, v_dinv, v_agg8, v_s, NVG, FV);
    layer1_combine<<<NPG, 256>>>(p_agg8, p_s, Mp, p_b1, p_tmp);
    layer1_combine<<<NVG, 256>>>(v_agg8, v_s, Mv, v_b1, v_tmp);

    // ---- layer 2: agg first, then GEMM (+b2) ----
    gcn_agg<<<(NPG + 7) / 8, 256>>>(p_tmp, p_csr, p_indeg, p_dinv, nullptr,
                                    nullptr, p_hi, p_lo, NPG, 0);
    gcn_agg<<<(NVG + 7) / 8, 256>>>(v_tmp, v_csr, v_indeg, v_dinv, nullptr,
                                    nullptr, v_hi, v_lo, NVG, 0);
    {
        dim3 gp(2, NPG / 128);
        gemm_smem<<<gp, 256, GEMM_SMEM>>>(p_hi, p_lo, wtp2h, wtp2l, p_b2, p_node);
        dim3 gv(2, NVG / 128);
        gemm_smem<<<gv, 256, GEMM_SMEM>>>(v_hi, v_lo, wtv2h, wtv2l, v_b2, v_node);
    }

    // ---- pooling + fuse ----
    pool_v_kernel<<<NB, 256>>>(v_node, vg);
    {
        dim3 g(NB, PPOOL);
        pool_p_partial<<<g, 256>>>(p_node, pgp);
    }
    addvec_kernel<<<NB, 256>>>(pgp, vg, v_node, v_init, curr, av);

    const int total4 = NPG * (DD / 4);
    final_kernel<<<(total4 + 255) / 256, 256>>>(p_node, p_x, p_initW, p_initb, av, out);
}